// round 2
// baseline (speedup 1.0000x reference)
#include <cuda_runtime.h>
#include <math.h>

static constexpr int B = 4, N = 2048, DIM = 768, H = 12, DH = 64, MLP = 3072, L = 2;
static constexpr int M = B * N;            // 8192 rows
static constexpr int HD = H * DH;          // 768

// ---------------- scratch (device globals; no allocation allowed) -------------
__device__ float g_x   [M * DIM];
__device__ float g_xn  [M * DIM];
__device__ float g_qlin[M * HD];
__device__ float g_kv  [M * 2 * HD];
__device__ float g_Q   [B * H * N * DH];
__device__ float g_K   [B * H * N * DH];
__device__ float g_V   [B * H * N * DH];
__device__ float g_att [M * HD];
__device__ float g_h   [M * MLP];

// ---------------- LayerNorm: one block per row, DIM=768 ----------------------
__global__ void ln_kernel(const float* __restrict__ in, const float* __restrict__ g,
                          float* __restrict__ out)
{
    __shared__ float red[256];
    int row = blockIdx.x;
    const float* x = in + (size_t)row * DIM;
    float v[3];
    float s = 0.f;
#pragma unroll
    for (int i = 0; i < 3; i++) { v[i] = x[threadIdx.x + i * 256]; s += v[i]; }
    red[threadIdx.x] = s; __syncthreads();
    for (int o = 128; o; o >>= 1) { if (threadIdx.x < o) red[threadIdx.x] += red[threadIdx.x + o]; __syncthreads(); }
    float mean = red[0] * (1.0f / DIM);
    __syncthreads();
    float s2 = 0.f;
#pragma unroll
    for (int i = 0; i < 3; i++) { float d = v[i] - mean; s2 += d * d; }
    red[threadIdx.x] = s2; __syncthreads();
    for (int o = 128; o; o >>= 1) { if (threadIdx.x < o) red[threadIdx.x] += red[threadIdx.x + o]; __syncthreads(); }
    float inv = rsqrtf(red[0] * (1.0f / DIM) + 1e-5f);
#pragma unroll
    for (int i = 0; i < 3; i++) {
        int c = threadIdx.x + i * 256;
        out[(size_t)row * DIM + c] = (v[i] - mean) * inv * g[c];
    }
}

// ---------------- GEMM: C[M,Nc] = A[M,K]@W[K,Nc] (+bias)(gelu)(+res) ---------
// mode bit0: +bias, bit1: gelu, bit2: +res
__global__ void gemm_kernel(const float* __restrict__ A, const float* __restrict__ W,
                            const float* __restrict__ bias, const float* __restrict__ res,
                            float* __restrict__ C, int K_, int Nc, int mode)
{
    __shared__ float As[16][65];
    __shared__ float Bs[16][64];
    int tx = threadIdx.x & 15, ty = threadIdx.x >> 4;
    int m0 = blockIdx.y * 64, n0 = blockIdx.x * 64;
    float acc[4][4] = {};
    for (int k0 = 0; k0 < K_; k0 += 16) {
#pragma unroll
        for (int i = 0; i < 4; i++) {
            int e = threadIdx.x + i * 256;
            int k = e & 15, mm = e >> 4;
            As[k][mm] = A[(size_t)(m0 + mm) * K_ + k0 + k];
        }
#pragma unroll
        for (int i = 0; i < 4; i++) {
            int e = threadIdx.x + i * 256;
            int nn = e & 63, k = e >> 6;
            Bs[k][nn] = W[(size_t)(k0 + k) * Nc + n0 + nn];
        }
        __syncthreads();
#pragma unroll
        for (int k = 0; k < 16; k++) {
            float a[4], b[4];
#pragma unroll
            for (int r = 0; r < 4; r++) a[r] = As[k][ty * 4 + r];
#pragma unroll
            for (int c = 0; c < 4; c++) b[c] = Bs[k][tx + 16 * c];
#pragma unroll
            for (int r = 0; r < 4; r++)
#pragma unroll
                for (int c = 0; c < 4; c++) acc[r][c] += a[r] * b[c];
        }
        __syncthreads();
    }
#pragma unroll
    for (int r = 0; r < 4; r++) {
        int mm = m0 + ty * 4 + r;
#pragma unroll
        for (int c = 0; c < 4; c++) {
            int nn = n0 + tx + 16 * c;
            float v = acc[r][c];
            if (mode & 1) v += bias[nn];
            if (mode & 2) v = 0.5f * v * (1.0f + erff(v * 0.70710678118654752f));
            if (mode & 4) v += res[(size_t)mm * Nc + nn];
            C[(size_t)mm * Nc + nn] = v;
        }
    }
}

// ------------- QK rmsnorm + 2D RoPE + V transpose; 1 warp per (b,h,n) --------
__global__ void qkv_prep(const float* __restrict__ qlin, const float* __restrict__ kv,
                         const float* __restrict__ qg, const float* __restrict__ kg,
                         const int* __restrict__ hidx, const int* __restrict__ widx,
                         float* __restrict__ Q, float* __restrict__ K, float* __restrict__ V)
{
    int warp = (blockIdx.x * blockDim.x + threadIdx.x) >> 5;
    int lane = threadIdx.x & 31;
    int n = warp % N;
    int bh = warp / N;
    int h = bh % H, b = bh / H;

    size_t qsrc = ((size_t)(b * N + n)) * HD + h * DH;
    size_t kvsrc = ((size_t)(b * N + n)) * (2 * HD) + h * DH;
    float q0 = qlin[qsrc + lane], q1 = qlin[qsrc + lane + 32];
    float k0 = kv[kvsrc + lane], k1 = kv[kvsrc + lane + 32];
    float v0 = kv[kvsrc + HD + lane], v1 = kv[kvsrc + HD + lane + 32];

    // rms norm: x / max(||x||,1e-12) * 8 * g
    float qs = q0 * q0 + q1 * q1;
    float ks = k0 * k0 + k1 * k1;
    for (int o = 16; o; o >>= 1) {
        qs += __shfl_xor_sync(0xffffffffu, qs, o);
        ks += __shfl_xor_sync(0xffffffffu, ks, o);
    }
    float rq = 8.0f / fmaxf(sqrtf(qs), 1e-12f);
    float rk = 8.0f / fmaxf(sqrtf(ks), 1e-12f);
    q0 = q0 * rq * qg[h * DH + lane];  q1 = q1 * rq * qg[h * DH + lane + 32];
    k0 = k0 * rk * kg[h * DH + lane];  k1 = k1 * rk * kg[h * DH + lane + 32];

    // 2D rope: dims [0,32) use h_idx, [32,64) use w_idx; pairs (f, f+16) within half
    int hv = hidx[b * N + n], wv = widx[b * N + n];
    int fi = lane & 15;
    float invf = __expf(-(float)fi * (9.210340371976184f / 16.0f)); // 10000^(-fi/16)
    float th_h = (float)hv * invf, th_w = (float)wv * invf;
    float sh, ch, sw, cw;
    __sincosf(th_h, &sh, &ch);
    __sincosf(th_w, &sw, &cw);
    float sgn = (lane < 16) ? -1.0f : 1.0f;
    float qp0 = __shfl_xor_sync(0xffffffffu, q0, 16);
    float qp1 = __shfl_xor_sync(0xffffffffu, q1, 16);
    float kp0 = __shfl_xor_sync(0xffffffffu, k0, 16);
    float kp1 = __shfl_xor_sync(0xffffffffu, k1, 16);
    q0 = q0 * ch + sgn * qp0 * sh;
    q1 = q1 * cw + sgn * qp1 * sw;
    k0 = k0 * ch + sgn * kp0 * sh;
    k1 = k1 * cw + sgn * kp1 * sw;

    size_t dst = ((size_t)bh * N + n) * DH;
    Q[dst + lane] = q0; Q[dst + lane + 32] = q1;
    K[dst + lane] = k0; K[dst + lane + 32] = k1;
    V[dst + lane] = v0; V[dst + lane + 32] = v1;
}

// ------------- attention: flash-style, 1 warp per query row ------------------
__global__ void attn_kernel(const float* __restrict__ Q, const float* __restrict__ K,
                            const float* __restrict__ V, const int* __restrict__ lengths,
                            float* __restrict__ O)
{
    __shared__ float Ks[32][65];
    __shared__ float Vs[32][64];
    __shared__ float qs[4][64];
    __shared__ float ps[4][32];
    int bh = blockIdx.y;
    int b = bh / H, h = bh % H;
    int w = threadIdx.x >> 5, lane = threadIdx.x & 31;
    int n = blockIdx.x * 4 + w;

    const float* qrow = Q + ((size_t)bh * N + n) * DH;
    qs[w][lane] = qrow[lane];
    qs[w][lane + 32] = qrow[lane + 32];
    int len = lengths[b];
    const float* Kb = K + (size_t)bh * N * DH;
    const float* Vb = V + (size_t)bh * N * DH;

    float m = -3.4e38f, l = 0.f, o0 = 0.f, o1 = 0.f;
    int ntiles = (len + 31) >> 5;
    for (int t = 0; t < ntiles; t++) {
        int j0 = t * 32;
        __syncthreads();
#pragma unroll
        for (int i = 0; i < 16; i++) {
            int e = threadIdx.x + i * 128;
            int j = e >> 6, d = e & 63;
            int jj = j0 + j; if (jj > N - 1) jj = N - 1;
            Ks[j][d] = Kb[(size_t)jj * DH + d];
            Vs[j][d] = Vb[(size_t)jj * DH + d];
        }
        __syncthreads();
        float s = 0.f;
#pragma unroll
        for (int d = 0; d < 64; d++) s += qs[w][d] * Ks[lane][d];
        bool valid = (j0 + lane) < len;
        if (!valid) s = -3.4e38f;
        float tm = s;
        for (int o = 16; o; o >>= 1) tm = fmaxf(tm, __shfl_xor_sync(0xffffffffu, tm, o));
        float mn = fmaxf(m, tm);
        float scale = __expf(m - mn);
        float p = valid ? __expf(s - mn) : 0.f;
        float psum = p;
        for (int o = 16; o; o >>= 1) psum += __shfl_xor_sync(0xffffffffu, psum, o);
        l = l * scale + psum;
        o0 *= scale; o1 *= scale;
        ps[w][lane] = p;
        __syncwarp();
#pragma unroll
        for (int j = 0; j < 32; j++) {
            float pj = ps[w][j];
            o0 += pj * Vs[j][lane];
            o1 += pj * Vs[j][lane + 32];
        }
        m = mn;
    }
    float invl = 1.0f / l;
    size_t dst = ((size_t)(b * N + n)) * HD + h * DH;
    O[dst + lane] = o0 * invl;
    O[dst + lane + 32] = o1 * invl;
}

// ------------- mask output ---------------------------------------------------
__global__ void mask_kernel(const int* __restrict__ lengths, float* __restrict__ out)
{
    int i = blockIdx.x * blockDim.x + threadIdx.x; // i in [0, B*N)
    int b = i / N, n = i % N;
    out[i] = (n < lengths[b]) ? 1.0f : 0.0f;
}

// -----------------------------------------------------------------------------
extern "C" void kernel_launch(void* const* d_in, const int* in_sizes, int n_in,
                              void* d_out, int out_size)
{
    const float* patches    = (const float*)d_in[0];
    const float* pe_ln1_g   = (const float*)d_in[1];
    const float* pe_W       = (const float*)d_in[2];
    const float* pe_b       = (const float*)d_in[3];
    const float* pe_ln2_g   = (const float*)d_in[4];
    const float* attn_ln_g  = (const float*)d_in[5];
    const float* qn_g       = (const float*)d_in[6];
    const float* kn_g       = (const float*)d_in[7];
    const float* Wq         = (const float*)d_in[8];
    const float* Wkv        = (const float*)d_in[9];
    const float* Wo         = (const float*)d_in[10];
    const float* ff_ln_g    = (const float*)d_in[11];
    const float* W1         = (const float*)d_in[12];
    const float* b1         = (const float*)d_in[13];
    const float* W2         = (const float*)d_in[14];
    const float* b2         = (const float*)d_in[15];
    const float* final_ln_g = (const float*)d_in[16];
    const int*   h_idx      = (const int*)d_in[17];
    const int*   w_idx      = (const int*)d_in[18];
    const int*   lengths    = (const int*)d_in[19];
    float* out = (float*)d_out;

    float *x, *xn, *qlin, *kv, *Qb, *Kb, *Vb, *att, *hb;
    cudaGetSymbolAddress((void**)&x, g_x);
    cudaGetSymbolAddress((void**)&xn, g_xn);
    cudaGetSymbolAddress((void**)&qlin, g_qlin);
    cudaGetSymbolAddress((void**)&kv, g_kv);
    cudaGetSymbolAddress((void**)&Qb, g_Q);
    cudaGetSymbolAddress((void**)&Kb, g_K);
    cudaGetSymbolAddress((void**)&Vb, g_V);
    cudaGetSymbolAddress((void**)&att, g_att);
    cudaGetSymbolAddress((void**)&hb, g_h);

    dim3 g12(DIM / 64, M / 64);   // Nc=768
    dim3 g24(2 * DIM / 64, M / 64); // Nc=1536
    dim3 g48(MLP / 64, M / 64);   // Nc=3072

    // patch embedding: LN -> Linear+bias -> LN
    ln_kernel<<<M, 256>>>(patches, pe_ln1_g, xn);
    gemm_kernel<<<g12, 256>>>(xn, pe_W, pe_b, nullptr, x, DIM, DIM, 1);
    ln_kernel<<<M, 256>>>(x, pe_ln2_g, x);

    for (int i = 0; i < L; i++) {
        const float* Wq_i  = Wq  + (size_t)i * DIM * HD;
        const float* Wkv_i = Wkv + (size_t)i * DIM * 2 * HD;
        const float* Wo_i  = Wo  + (size_t)i * HD * DIM;
        const float* W1_i  = W1  + (size_t)i * DIM * MLP;
        const float* W2_i  = W2  + (size_t)i * MLP * DIM;

        ln_kernel<<<M, 256>>>(x, attn_ln_g + i * DIM, xn);
        gemm_kernel<<<g12, 256>>>(xn, Wq_i, nullptr, nullptr, qlin, DIM, HD, 0);
        gemm_kernel<<<g24, 256>>>(xn, Wkv_i, nullptr, nullptr, kv, DIM, 2 * HD, 0);
        qkv_prep<<<(B * H * N) / 8, 256>>>(qlin, kv, qn_g + i * H * DH, kn_g + i * H * DH,
                                           h_idx, w_idx, Qb, Kb, Vb);
        attn_kernel<<<dim3(N / 4, B * H), 128>>>(Qb, Kb, Vb, lengths, att);
        gemm_kernel<<<g12, 256>>>(att, Wo_i, nullptr, x, x, HD, DIM, 4);
        ln_kernel<<<M, 256>>>(x, ff_ln_g + i * DIM, xn);
        gemm_kernel<<<g48, 256>>>(xn, W1_i, b1 + i * MLP, nullptr, hb, DIM, MLP, 3);
        gemm_kernel<<<g12, 256>>>(hb, W2_i, b2 + i * DIM, x, x, MLP, DIM, 5);
    }

    ln_kernel<<<M, 256>>>(x, final_ln_g, out);
    if (out_size >= M * DIM + B * N) {
        mask_kernel<<<(B * N) / 256, 256>>>(lengths, out + (size_t)M * DIM);
    }
}

// round 4
// speedup vs baseline: 1.5029x; 1.5029x over previous
#include <cuda_runtime.h>
#include <math.h>

static constexpr int B = 4, N = 2048, DIM = 768, H = 12, DH = 64, MLP = 3072, L = 2;
static constexpr int M = B * N;            // 8192 rows
static constexpr int HD = H * DH;          // 768

// ---------------- scratch (device globals; no allocation allowed) -------------
__device__ float g_x   [M * DIM];
__device__ float g_xn  [M * DIM];
__device__ float g_qlin[M * HD];
__device__ float g_kv  [M * 2 * HD];
__device__ float g_Q   [B * H * N * DH];
__device__ float g_K   [B * H * N * DH];
__device__ float g_V   [B * H * N * DH];
__device__ float g_att [M * HD];
__device__ float g_h   [M * MLP];

// ---------------- LayerNorm: one block per row, DIM=768 ----------------------
__global__ void ln_kernel(const float* __restrict__ in, const float* __restrict__ g,
                          float* __restrict__ out)
{
    __shared__ float red[256];
    int row = blockIdx.x;
    const float* x = in + (size_t)row * DIM;
    float v[3];
    float s = 0.f;
#pragma unroll
    for (int i = 0; i < 3; i++) { v[i] = x[threadIdx.x + i * 256]; s += v[i]; }
    red[threadIdx.x] = s; __syncthreads();
    for (int o = 128; o; o >>= 1) { if (threadIdx.x < o) red[threadIdx.x] += red[threadIdx.x + o]; __syncthreads(); }
    float mean = red[0] * (1.0f / DIM);
    __syncthreads();
    float s2 = 0.f;
#pragma unroll
    for (int i = 0; i < 3; i++) { float d = v[i] - mean; s2 += d * d; }
    red[threadIdx.x] = s2; __syncthreads();
    for (int o = 128; o; o >>= 1) { if (threadIdx.x < o) red[threadIdx.x] += red[threadIdx.x + o]; __syncthreads(); }
    float inv = rsqrtf(red[0] * (1.0f / DIM) + 1e-5f);
#pragma unroll
    for (int i = 0; i < 3; i++) {
        int c = threadIdx.x + i * 256;
        out[(size_t)row * DIM + c] = (v[i] - mean) * inv * g[c];
    }
}

// ---------------- tf32 tensor-core GEMM --------------------------------------
// C[M,Nc] = A[M,K] @ W[K,Nc], mode bit0:+bias, bit1:gelu, bit2:+res
// Block tile 128x128, BK=32. 256 threads = 8 warps; warp tile 32x64.
// mma.sync.aligned.m16n8k8.row.col.f32.tf32.tf32.f32

__device__ __forceinline__ unsigned f2tf(float f) {
    unsigned u; asm("cvt.rna.tf32.f32 %0, %1;" : "=r"(u) : "f"(f)); return u;
}

__device__ __forceinline__ void mma_tf32(float* c, const unsigned* a, unsigned b0, unsigned b1) {
    asm volatile("mma.sync.aligned.m16n8k8.row.col.f32.tf32.tf32.f32 "
                 "{%0,%1,%2,%3}, {%4,%5,%6,%7}, {%8,%9}, {%0,%1,%2,%3};"
                 : "+f"(c[0]), "+f"(c[1]), "+f"(c[2]), "+f"(c[3])
                 : "r"(a[0]), "r"(a[1]), "r"(a[2]), "r"(a[3]), "r"(b0), "r"(b1));
}

#define GBM 128
#define GBN 128
#define GBK 32
#define A_LD 36   // pad: bank = group*4 + tid -> conflict-free frag loads
#define B_LD 136  // pad: bank = tid*8 + group -> conflict-free frag loads

__global__ __launch_bounds__(256, 2)
void gemm_mma(const float* __restrict__ A, const float* __restrict__ W,
              const float* __restrict__ bias, const float* __restrict__ res,
              float* __restrict__ C, int K_, int Nc, int mode)
{
    __shared__ unsigned As[GBM * A_LD];
    __shared__ unsigned Bs[GBK * B_LD];

    int t = threadIdx.x;
    int warp = t >> 5, lane = t & 31;
    int group = lane >> 2, tid = lane & 3;
    int wm = warp >> 1, wn = warp & 1;        // warp grid 4x2
    int wr = wm * 32, wc = wn * 64;           // warp tile 32x64
    int m0 = blockIdx.y * GBM, n0 = blockIdx.x * GBN;

    float acc[2][8][4];
#pragma unroll
    for (int a = 0; a < 2; a++)
#pragma unroll
        for (int b = 0; b < 8; b++)
#pragma unroll
            for (int c = 0; c < 4; c++) acc[a][b][c] = 0.f;

    int KT = K_ / GBK;
    for (int kt = 0; kt < KT; kt++) {
        int k0 = kt * GBK;
        // stage A: 128 rows x 32 cols, float4 loads, tf32 convert
        const float* Ab = A + (size_t)m0 * K_ + k0;
#pragma unroll
        for (int i = 0; i < 4; i++) {
            int idx = t + i * 256;
            int row = idx >> 3, k4 = (idx & 7) * 4;
            float4 v = *(const float4*)(Ab + (size_t)row * K_ + k4);
            uint4 u = { f2tf(v.x), f2tf(v.y), f2tf(v.z), f2tf(v.w) };
            *(uint4*)&As[row * A_LD + k4] = u;
        }
        // stage B: 32 rows x 128 cols
        const float* Bb = W + (size_t)k0 * Nc + n0;
#pragma unroll
        for (int i = 0; i < 4; i++) {
            int idx = t + i * 256;
            int kr = idx >> 5, n4 = (idx & 31) * 4;
            float4 v = *(const float4*)(Bb + (size_t)kr * Nc + n4);
            uint4 u = { f2tf(v.x), f2tf(v.y), f2tf(v.z), f2tf(v.w) };
            *(uint4*)&Bs[kr * B_LD + n4] = u;
        }
        __syncthreads();
#pragma unroll
        for (int kk = 0; kk < 4; kk++) {
            int k8 = kk * 8;
            unsigned a[2][4];
#pragma unroll
            for (int mt = 0; mt < 2; mt++) {
                int r0 = wr + mt * 16;
                a[mt][0] = As[(r0 + group) * A_LD + k8 + tid];
                a[mt][1] = As[(r0 + 8 + group) * A_LD + k8 + tid];
                a[mt][2] = As[(r0 + group) * A_LD + k8 + tid + 4];
                a[mt][3] = As[(r0 + 8 + group) * A_LD + k8 + tid + 4];
            }
#pragma unroll
            for (int nt = 0; nt < 8; nt++) {
                unsigned b0 = Bs[(k8 + tid) * B_LD + wc + nt * 8 + group];
                unsigned b1 = Bs[(k8 + tid + 4) * B_LD + wc + nt * 8 + group];
                mma_tf32(acc[0][nt], a[0], b0, b1);
                mma_tf32(acc[1][nt], a[1], b0, b1);
            }
        }
        __syncthreads();
    }

    // epilogue
#pragma unroll
    for (int mt = 0; mt < 2; mt++) {
#pragma unroll
        for (int half = 0; half < 2; half++) {
            int r = m0 + wr + mt * 16 + half * 8 + group;
#pragma unroll
            for (int nt = 0; nt < 8; nt++) {
                int c = n0 + wc + nt * 8 + tid * 2;
                float v0 = acc[mt][nt][half * 2 + 0];
                float v1 = acc[mt][nt][half * 2 + 1];
                if (mode & 1) { v0 += bias[c]; v1 += bias[c + 1]; }
                if (mode & 2) {
                    v0 = 0.5f * v0 * (1.0f + erff(v0 * 0.70710678118654752f));
                    v1 = 0.5f * v1 * (1.0f + erff(v1 * 0.70710678118654752f));
                }
                if (mode & 4) {
                    float2 rr = *(const float2*)(res + (size_t)r * Nc + c);
                    v0 += rr.x; v1 += rr.y;
                }
                float2 o = { v0, v1 };
                *(float2*)(C + (size_t)r * Nc + c) = o;
            }
        }
    }
}

// ------------- QK rmsnorm + 2D RoPE + V transpose; 1 warp per (b,h,n) --------
__global__ void qkv_prep(const float* __restrict__ qlin, const float* __restrict__ kv,
                         const float* __restrict__ qg, const float* __restrict__ kg,
                         const int* __restrict__ hidx, const int* __restrict__ widx,
                         float* __restrict__ Q, float* __restrict__ K, float* __restrict__ V)
{
    int warp = (blockIdx.x * blockDim.x + threadIdx.x) >> 5;
    int lane = threadIdx.x & 31;
    int n = warp % N;
    int bh = warp / N;
    int h = bh % H, b = bh / H;

    size_t qsrc = ((size_t)(b * N + n)) * HD + h * DH;
    size_t kvsrc = ((size_t)(b * N + n)) * (2 * HD) + h * DH;
    float q0 = qlin[qsrc + lane], q1 = qlin[qsrc + lane + 32];
    float k0 = kv[kvsrc + lane], k1 = kv[kvsrc + lane + 32];
    float v0 = kv[kvsrc + HD + lane], v1 = kv[kvsrc + HD + lane + 32];

    float qs = q0 * q0 + q1 * q1;
    float ks = k0 * k0 + k1 * k1;
    for (int o = 16; o; o >>= 1) {
        qs += __shfl_xor_sync(0xffffffffu, qs, o);
        ks += __shfl_xor_sync(0xffffffffu, ks, o);
    }
    float rq = 8.0f / fmaxf(sqrtf(qs), 1e-12f);
    float rk = 8.0f / fmaxf(sqrtf(ks), 1e-12f);
    q0 = q0 * rq * qg[h * DH + lane];  q1 = q1 * rq * qg[h * DH + lane + 32];
    k0 = k0 * rk * kg[h * DH + lane];  k1 = k1 * rk * kg[h * DH + lane + 32];

    int hv = hidx[b * N + n], wv = widx[b * N + n];
    int fi = lane & 15;
    float invf = __expf(-(float)fi * (9.210340371976184f / 16.0f));
    float th_h = (float)hv * invf, th_w = (float)wv * invf;
    float sh, ch, sw, cw;
    __sincosf(th_h, &sh, &ch);
    __sincosf(th_w, &sw, &cw);
    float sgn = (lane < 16) ? -1.0f : 1.0f;
    float qp0 = __shfl_xor_sync(0xffffffffu, q0, 16);
    float qp1 = __shfl_xor_sync(0xffffffffu, q1, 16);
    float kp0 = __shfl_xor_sync(0xffffffffu, k0, 16);
    float kp1 = __shfl_xor_sync(0xffffffffu, k1, 16);
    q0 = q0 * ch + sgn * qp0 * sh;
    q1 = q1 * cw + sgn * qp1 * sw;
    k0 = k0 * ch + sgn * kp0 * sh;
    k1 = k1 * cw + sgn * kp1 * sw;

    size_t dst = ((size_t)bh * N + n) * DH;
    Q[dst + lane] = q0; Q[dst + lane + 32] = q1;
    K[dst + lane] = k0; K[dst + lane + 32] = k1;
    V[dst + lane] = v0; V[dst + lane + 32] = v1;
}

// ------------- attention: flash-style, 1 warp per query row ------------------
__global__ void attn_kernel(const float* __restrict__ Q, const float* __restrict__ K,
                            const float* __restrict__ V, const int* __restrict__ lengths,
                            float* __restrict__ O)
{
    __shared__ float Ks[32][65];
    __shared__ float Vs[32][64];
    __shared__ float qs[4][64];
    __shared__ float ps[4][32];
    int bh = blockIdx.y;
    int b = bh / H, h = bh % H;
    int w = threadIdx.x >> 5, lane = threadIdx.x & 31;
    int n = blockIdx.x * 4 + w;

    const float* qrow = Q + ((size_t)bh * N + n) * DH;
    qs[w][lane] = qrow[lane];
    qs[w][lane + 32] = qrow[lane + 32];
    int len = lengths[b];
    const float* Kb = K + (size_t)bh * N * DH;
    const float* Vb = V + (size_t)bh * N * DH;

    float m = -3.4e38f, l = 0.f, o0 = 0.f, o1 = 0.f;
    int ntiles = (len + 31) >> 5;
    for (int t = 0; t < ntiles; t++) {
        int j0 = t * 32;
        __syncthreads();
#pragma unroll
        for (int i = 0; i < 16; i++) {
            int e = threadIdx.x + i * 128;
            int j = e >> 6, d = e & 63;
            int jj = j0 + j; if (jj > N - 1) jj = N - 1;
            Ks[j][d] = Kb[(size_t)jj * DH + d];
            Vs[j][d] = Vb[(size_t)jj * DH + d];
        }
        __syncthreads();
        float s = 0.f;
#pragma unroll
        for (int d = 0; d < 64; d++) s += qs[w][d] * Ks[lane][d];
        bool valid = (j0 + lane) < len;
        if (!valid) s = -3.4e38f;
        float tm = s;
        for (int o = 16; o; o >>= 1) tm = fmaxf(tm, __shfl_xor_sync(0xffffffffu, tm, o));
        float mn = fmaxf(m, tm);
        float scale = __expf(m - mn);
        float p = valid ? __expf(s - mn) : 0.f;
        float psum = p;
        for (int o = 16; o; o >>= 1) psum += __shfl_xor_sync(0xffffffffu, psum, o);
        l = l * scale + psum;
        o0 *= scale; o1 *= scale;
        ps[w][lane] = p;
        __syncwarp();
#pragma unroll
        for (int j = 0; j < 32; j++) {
            float pj = ps[w][j];
            o0 += pj * Vs[j][lane];
            o1 += pj * Vs[j][lane + 32];
        }
        m = mn;
    }
    float invl = 1.0f / l;
    size_t dst = ((size_t)(b * N + n)) * HD + h * DH;
    O[dst + lane] = o0 * invl;
    O[dst + lane + 32] = o1 * invl;
}

// ------------- mask output ---------------------------------------------------
__global__ void mask_kernel(const int* __restrict__ lengths, float* __restrict__ out)
{
    int i = blockIdx.x * blockDim.x + threadIdx.x;
    int b = i / N, n = i % N;
    out[i] = (n < lengths[b]) ? 1.0f : 0.0f;
}

// -----------------------------------------------------------------------------
extern "C" void kernel_launch(void* const* d_in, const int* in_sizes, int n_in,
                              void* d_out, int out_size)
{
    const float* patches    = (const float*)d_in[0];
    const float* pe_ln1_g   = (const float*)d_in[1];
    const float* pe_W       = (const float*)d_in[2];
    const float* pe_b       = (const float*)d_in[3];
    const float* pe_ln2_g   = (const float*)d_in[4];
    const float* attn_ln_g  = (const float*)d_in[5];
    const float* qn_g       = (const float*)d_in[6];
    const float* kn_g       = (const float*)d_in[7];
    const float* Wq         = (const float*)d_in[8];
    const float* Wkv        = (const float*)d_in[9];
    const float* Wo         = (const float*)d_in[10];
    const float* ff_ln_g    = (const float*)d_in[11];
    const float* W1         = (const float*)d_in[12];
    const float* b1         = (const float*)d_in[13];
    const float* W2         = (const float*)d_in[14];
    const float* b2         = (const float*)d_in[15];
    const float* final_ln_g = (const float*)d_in[16];
    const int*   h_idx      = (const int*)d_in[17];
    const int*   w_idx      = (const int*)d_in[18];
    const int*   lengths    = (const int*)d_in[19];
    float* out = (float*)d_out;

    float *x, *xn, *qlin, *kv, *Qb, *Kb, *Vb, *att, *hb;
    cudaGetSymbolAddress((void**)&x, g_x);
    cudaGetSymbolAddress((void**)&xn, g_xn);
    cudaGetSymbolAddress((void**)&qlin, g_qlin);
    cudaGetSymbolAddress((void**)&kv, g_kv);
    cudaGetSymbolAddress((void**)&Qb, g_Q);
    cudaGetSymbolAddress((void**)&Kb, g_K);
    cudaGetSymbolAddress((void**)&Vb, g_V);
    cudaGetSymbolAddress((void**)&att, g_att);
    cudaGetSymbolAddress((void**)&hb, g_h);

    dim3 gDIM(DIM / 128, M / 128);       // Nc=768
    dim3 gKV(2 * HD / 128, M / 128);     // Nc=1536
    dim3 gMLP(MLP / 128, M / 128);       // Nc=3072

    // patch embedding: LN -> Linear+bias -> LN
    ln_kernel<<<M, 256>>>(patches, pe_ln1_g, xn);
    gemm_mma<<<gDIM, 256>>>(xn, pe_W, pe_b, nullptr, x, DIM, DIM, 1);
    ln_kernel<<<M, 256>>>(x, pe_ln2_g, x);

    for (int i = 0; i < L; i++) {
        const float* Wq_i  = Wq  + (size_t)i * DIM * HD;
        const float* Wkv_i = Wkv + (size_t)i * DIM * 2 * HD;
        const float* Wo_i  = Wo  + (size_t)i * HD * DIM;
        const float* W1_i  = W1  + (size_t)i * DIM * MLP;
        const float* W2_i  = W2  + (size_t)i * MLP * DIM;

        ln_kernel<<<M, 256>>>(x, attn_ln_g + i * DIM, xn);
        gemm_mma<<<gDIM, 256>>>(xn, Wq_i, nullptr, nullptr, qlin, DIM, HD, 0);
        gemm_mma<<<gKV, 256>>>(xn, Wkv_i, nullptr, nullptr, kv, DIM, 2 * HD, 0);
        qkv_prep<<<(B * H * N) / 8, 256>>>(qlin, kv, qn_g + i * H * DH, kn_g + i * H * DH,
                                           h_idx, w_idx, Qb, Kb, Vb);
        attn_kernel<<<dim3(N / 4, B * H), 128>>>(Qb, Kb, Vb, lengths, att);
        gemm_mma<<<gDIM, 256>>>(att, Wo_i, nullptr, x, x, HD, DIM, 4);
        ln_kernel<<<M, 256>>>(x, ff_ln_g + i * DIM, xn);
        gemm_mma<<<gMLP, 256>>>(xn, W1_i, b1 + i * MLP, nullptr, hb, DIM, MLP, 3);
        gemm_mma<<<gDIM, 256>>>(hb, W2_i, b2 + i * DIM, x, x, MLP, DIM, 5);
    }

    ln_kernel<<<M, 256>>>(x, final_ln_g, out);
    if (out_size >= M * DIM + B * N) {
        mask_kernel<<<(B * N) / 256, 256>>>(lengths, out + (size_t)M * DIM);
    }
}

// round 5
// speedup vs baseline: 4.4427x; 2.9562x over previous
#include <cuda_runtime.h>
#include <math.h>

static constexpr int B = 4, N = 2048, DIM = 768, H = 12, DH = 64, MLP = 3072, L = 2;
static constexpr int M = B * N;            // 8192 rows
static constexpr int HD = H * DH;          // 768

// ---------------- scratch (device globals; no allocation allowed) -------------
__device__ float g_x   [M * DIM];
__device__ float g_xn  [M * DIM];
__device__ float g_qlin[M * HD];
__device__ float g_kv  [M * 2 * HD];
__device__ float g_Q   [B * H * N * DH];
__device__ float g_K   [B * H * N * DH];
__device__ float g_V   [B * H * N * DH];
__device__ float g_att [M * HD];
__device__ float g_h   [M * MLP];

// ---------------- LayerNorm: one block per row, DIM=768 ----------------------
__global__ void ln_kernel(const float* __restrict__ in, const float* __restrict__ g,
                          float* __restrict__ out)
{
    __shared__ float red[256];
    int row = blockIdx.x;
    const float* x = in + (size_t)row * DIM;
    float v[3];
    float s = 0.f;
#pragma unroll
    for (int i = 0; i < 3; i++) { v[i] = x[threadIdx.x + i * 256]; s += v[i]; }
    red[threadIdx.x] = s; __syncthreads();
    for (int o = 128; o; o >>= 1) { if (threadIdx.x < o) red[threadIdx.x] += red[threadIdx.x + o]; __syncthreads(); }
    float mean = red[0] * (1.0f / DIM);
    __syncthreads();
    float s2 = 0.f;
#pragma unroll
    for (int i = 0; i < 3; i++) { float d = v[i] - mean; s2 += d * d; }
    red[threadIdx.x] = s2; __syncthreads();
    for (int o = 128; o; o >>= 1) { if (threadIdx.x < o) red[threadIdx.x] += red[threadIdx.x + o]; __syncthreads(); }
    float inv = rsqrtf(red[0] * (1.0f / DIM) + 1e-5f);
#pragma unroll
    for (int i = 0; i < 3; i++) {
        int c = threadIdx.x + i * 256;
        out[(size_t)row * DIM + c] = (v[i] - mean) * inv * g[c];
    }
}

// ---------------- tf32 helpers ------------------------------------------------
__device__ __forceinline__ unsigned f2tf(float f) {
    unsigned u; asm("cvt.rna.tf32.f32 %0, %1;" : "=r"(u) : "f"(f)); return u;
}

__device__ __forceinline__ void mma_tf32(float* c, const unsigned* a, unsigned b0, unsigned b1) {
    asm volatile("mma.sync.aligned.m16n8k8.row.col.f32.tf32.tf32.f32 "
                 "{%0,%1,%2,%3}, {%4,%5,%6,%7}, {%8,%9}, {%0,%1,%2,%3};"
                 : "+f"(c[0]), "+f"(c[1]), "+f"(c[2]), "+f"(c[3])
                 : "r"(a[0]), "r"(a[1]), "r"(a[2]), "r"(a[3]), "r"(b0), "r"(b1));
}

// ---------------- tf32 tensor-core GEMM --------------------------------------
#define GBM 128
#define GBN 128
#define GBK 32
#define A_LD 36
#define B_LD 136

__global__ __launch_bounds__(256, 2)
void gemm_mma(const float* __restrict__ A, const float* __restrict__ W,
              const float* __restrict__ bias, const float* __restrict__ res,
              float* __restrict__ C, int K_, int Nc, int mode)
{
    __shared__ unsigned As[GBM * A_LD];
    __shared__ unsigned Bs[GBK * B_LD];

    int t = threadIdx.x;
    int warp = t >> 5, lane = t & 31;
    int group = lane >> 2, tid = lane & 3;
    int wm = warp >> 1, wn = warp & 1;
    int wr = wm * 32, wc = wn * 64;
    int m0 = blockIdx.y * GBM, n0 = blockIdx.x * GBN;

    float acc[2][8][4];
#pragma unroll
    for (int a = 0; a < 2; a++)
#pragma unroll
        for (int b = 0; b < 8; b++)
#pragma unroll
            for (int c = 0; c < 4; c++) acc[a][b][c] = 0.f;

    int KT = K_ / GBK;
    for (int kt = 0; kt < KT; kt++) {
        int k0 = kt * GBK;
        const float* Ab = A + (size_t)m0 * K_ + k0;
#pragma unroll
        for (int i = 0; i < 4; i++) {
            int idx = t + i * 256;
            int row = idx >> 3, k4 = (idx & 7) * 4;
            float4 v = *(const float4*)(Ab + (size_t)row * K_ + k4);
            uint4 u = { f2tf(v.x), f2tf(v.y), f2tf(v.z), f2tf(v.w) };
            *(uint4*)&As[row * A_LD + k4] = u;
        }
        const float* Bb = W + (size_t)k0 * Nc + n0;
#pragma unroll
        for (int i = 0; i < 4; i++) {
            int idx = t + i * 256;
            int kr = idx >> 5, n4 = (idx & 31) * 4;
            float4 v = *(const float4*)(Bb + (size_t)kr * Nc + n4);
            uint4 u = { f2tf(v.x), f2tf(v.y), f2tf(v.z), f2tf(v.w) };
            *(uint4*)&Bs[kr * B_LD + n4] = u;
        }
        __syncthreads();
#pragma unroll
        for (int kk = 0; kk < 4; kk++) {
            int k8 = kk * 8;
            unsigned a[2][4];
#pragma unroll
            for (int mt = 0; mt < 2; mt++) {
                int r0 = wr + mt * 16;
                a[mt][0] = As[(r0 + group) * A_LD + k8 + tid];
                a[mt][1] = As[(r0 + 8 + group) * A_LD + k8 + tid];
                a[mt][2] = As[(r0 + group) * A_LD + k8 + tid + 4];
                a[mt][3] = As[(r0 + 8 + group) * A_LD + k8 + tid + 4];
            }
#pragma unroll
            for (int nt = 0; nt < 8; nt++) {
                unsigned b0 = Bs[(k8 + tid) * B_LD + wc + nt * 8 + group];
                unsigned b1 = Bs[(k8 + tid + 4) * B_LD + wc + nt * 8 + group];
                mma_tf32(acc[0][nt], a[0], b0, b1);
                mma_tf32(acc[1][nt], a[1], b0, b1);
            }
        }
        __syncthreads();
    }

#pragma unroll
    for (int mt = 0; mt < 2; mt++) {
#pragma unroll
        for (int half = 0; half < 2; half++) {
            int r = m0 + wr + mt * 16 + half * 8 + group;
#pragma unroll
            for (int nt = 0; nt < 8; nt++) {
                int c = n0 + wc + nt * 8 + tid * 2;
                float v0 = acc[mt][nt][half * 2 + 0];
                float v1 = acc[mt][nt][half * 2 + 1];
                if (mode & 1) { v0 += bias[c]; v1 += bias[c + 1]; }
                if (mode & 2) {
                    v0 = 0.5f * v0 * (1.0f + erff(v0 * 0.70710678118654752f));
                    v1 = 0.5f * v1 * (1.0f + erff(v1 * 0.70710678118654752f));
                }
                if (mode & 4) {
                    float2 rr = *(const float2*)(res + (size_t)r * Nc + c);
                    v0 += rr.x; v1 += rr.y;
                }
                float2 o = { v0, v1 };
                *(float2*)(C + (size_t)r * Nc + c) = o;
            }
        }
    }
}

// ------------- QK rmsnorm + 2D RoPE + V transpose; 1 warp per (b,h,n) --------
__global__ void qkv_prep(const float* __restrict__ qlin, const float* __restrict__ kv,
                         const float* __restrict__ qg, const float* __restrict__ kg,
                         const int* __restrict__ hidx, const int* __restrict__ widx,
                         float* __restrict__ Q, float* __restrict__ K, float* __restrict__ V)
{
    int warp = (blockIdx.x * blockDim.x + threadIdx.x) >> 5;
    int lane = threadIdx.x & 31;
    int n = warp % N;
    int bh = warp / N;
    int h = bh % H, b = bh / H;

    size_t qsrc = ((size_t)(b * N + n)) * HD + h * DH;
    size_t kvsrc = ((size_t)(b * N + n)) * (2 * HD) + h * DH;
    float q0 = qlin[qsrc + lane], q1 = qlin[qsrc + lane + 32];
    float k0 = kv[kvsrc + lane], k1 = kv[kvsrc + lane + 32];
    float v0 = kv[kvsrc + HD + lane], v1 = kv[kvsrc + HD + lane + 32];

    float qs = q0 * q0 + q1 * q1;
    float ks = k0 * k0 + k1 * k1;
    for (int o = 16; o; o >>= 1) {
        qs += __shfl_xor_sync(0xffffffffu, qs, o);
        ks += __shfl_xor_sync(0xffffffffu, ks, o);
    }
    float rq = 8.0f / fmaxf(sqrtf(qs), 1e-12f);
    float rk = 8.0f / fmaxf(sqrtf(ks), 1e-12f);
    q0 = q0 * rq * qg[h * DH + lane];  q1 = q1 * rq * qg[h * DH + lane + 32];
    k0 = k0 * rk * kg[h * DH + lane];  k1 = k1 * rk * kg[h * DH + lane + 32];

    int hv = hidx[b * N + n], wv = widx[b * N + n];
    int fi = lane & 15;
    float invf = __expf(-(float)fi * (9.210340371976184f / 16.0f));
    float th_h = (float)hv * invf, th_w = (float)wv * invf;
    float sh, ch, sw, cw;
    __sincosf(th_h, &sh, &ch);
    __sincosf(th_w, &sw, &cw);
    float sgn = (lane < 16) ? -1.0f : 1.0f;
    float qp0 = __shfl_xor_sync(0xffffffffu, q0, 16);
    float qp1 = __shfl_xor_sync(0xffffffffu, q1, 16);
    float kp0 = __shfl_xor_sync(0xffffffffu, k0, 16);
    float kp1 = __shfl_xor_sync(0xffffffffu, k1, 16);
    q0 = q0 * ch + sgn * qp0 * sh;
    q1 = q1 * cw + sgn * qp1 * sw;
    k0 = k0 * ch + sgn * kp0 * sh;
    k1 = k1 * cw + sgn * kp1 * sw;

    size_t dst = ((size_t)bh * N + n) * DH;
    Q[dst + lane] = q0; Q[dst + lane + 32] = q1;
    K[dst + lane] = k0; K[dst + lane + 32] = k1;
    V[dst + lane] = v0; V[dst + lane + 32] = v1;
}

// ------------- attention: mma flash, 64 queries/block, 64-key tiles ----------
// QK via 3xTF32 split (≈fp32), PV via 2x split on V.
#define KS_LD 68   // ≡4 mod 32: (key=g)*LD + t conflict-free
#define VS_LD 72   // ≡8 mod 32: (key=t)*LD + g conflict-free

__global__ __launch_bounds__(128, 2)
void attn_mma(const float* __restrict__ Q, const float* __restrict__ K,
              const float* __restrict__ V, const int* __restrict__ lengths,
              float* __restrict__ O)
{
    extern __shared__ float sm[];
    float* Khi = sm;                    // 64*KS_LD
    float* Klo = Khi + 64 * KS_LD;
    float* Vhi = Klo + 64 * KS_LD;      // 64*VS_LD
    float* Vlo = Vhi + 64 * VS_LD;

    int bh = blockIdx.y;
    int b = bh / H, h = bh % H;
    int warp = threadIdx.x >> 5, lane = threadIdx.x & 31;
    int g = lane >> 2, t = lane & 3;
    int q0 = blockIdx.x * 64 + warp * 16;
    int len = lengths[b];

    const float* Qb = Q + (size_t)bh * N * DH;
    const float* Kb = K + (size_t)bh * N * DH;
    const float* Vb = V + (size_t)bh * N * DH;

    // Q fragments, split hi/lo once (A layout for m16n8k8)
    unsigned qhi[8][4], qlo[8][4];
#pragma unroll
    for (int kk = 0; kk < 8; kk++) {
        float f0 = Qb[(size_t)(q0 + g)     * DH + kk * 8 + t];
        float f1 = Qb[(size_t)(q0 + 8 + g) * DH + kk * 8 + t];
        float f2 = Qb[(size_t)(q0 + g)     * DH + kk * 8 + t + 4];
        float f3 = Qb[(size_t)(q0 + 8 + g) * DH + kk * 8 + t + 4];
        qhi[kk][0] = f2tf(f0); qlo[kk][0] = f2tf(f0 - __uint_as_float(qhi[kk][0]));
        qhi[kk][1] = f2tf(f1); qlo[kk][1] = f2tf(f1 - __uint_as_float(qhi[kk][1]));
        qhi[kk][2] = f2tf(f2); qlo[kk][2] = f2tf(f2 - __uint_as_float(qhi[kk][2]));
        qhi[kk][3] = f2tf(f3); qlo[kk][3] = f2tf(f3 - __uint_as_float(qhi[kk][3]));
    }

    float oacc[8][4];
#pragma unroll
    for (int dt = 0; dt < 8; dt++)
#pragma unroll
        for (int i = 0; i < 4; i++) oacc[dt][i] = 0.f;
    float m0 = -1e30f, m1 = -1e30f, l0 = 0.f, l1 = 0.f;

    for (int k0 = 0; k0 < len; k0 += 64) {
        __syncthreads();
        // stage K,V: 64 rows x 64 dims, float4 per thread x 8
#pragma unroll
        for (int i = 0; i < 8; i++) {
            int idx = threadIdx.x + i * 128;
            int row = idx >> 4, c4 = (idx & 15) * 4;
            int jj = k0 + row; if (jj > N - 1) jj = N - 1;
            float4 kv4 = *(const float4*)(Kb + (size_t)jj * DH + c4);
            float4 vv4 = *(const float4*)(Vb + (size_t)jj * DH + c4);
            float* kh = Khi + row * KS_LD + c4;
            float* kl = Klo + row * KS_LD + c4;
            float* vh = Vhi + row * VS_LD + c4;
            float* vl = Vlo + row * VS_LD + c4;
            float kvv[4] = { kv4.x, kv4.y, kv4.z, kv4.w };
            float vvv[4] = { vv4.x, vv4.y, vv4.z, vv4.w };
#pragma unroll
            for (int j = 0; j < 4; j++) {
                unsigned hbits = f2tf(kvv[j]);
                kh[j] = __uint_as_float(hbits);
                kl[j] = __uint_as_float(f2tf(kvv[j] - __uint_as_float(hbits)));
                unsigned vb = f2tf(vvv[j]);
                vh[j] = __uint_as_float(vb);
                vl[j] = __uint_as_float(f2tf(vvv[j] - __uint_as_float(vb)));
            }
        }
        __syncthreads();

        // S = Q K^T   (3x tf32)
        float sc[8][4];
#pragma unroll
        for (int nt = 0; nt < 8; nt++)
#pragma unroll
            for (int i = 0; i < 4; i++) sc[nt][i] = 0.f;
#pragma unroll
        for (int kk = 0; kk < 8; kk++) {
#pragma unroll
            for (int nt = 0; nt < 8; nt++) {
                int kb = (nt * 8 + g) * KS_LD + kk * 8 + t;
                unsigned bh0 = __float_as_uint(Khi[kb]);
                unsigned bh1 = __float_as_uint(Khi[kb + 4]);
                unsigned bl0 = __float_as_uint(Klo[kb]);
                unsigned bl1 = __float_as_uint(Klo[kb + 4]);
                mma_tf32(sc[nt], qhi[kk], bh0, bh1);
                mma_tf32(sc[nt], qhi[kk], bl0, bl1);
                mma_tf32(sc[nt], qlo[kk], bh0, bh1);
            }
        }

        // mask + online softmax
        float mx0 = -1e30f, mx1 = -1e30f;
#pragma unroll
        for (int nt = 0; nt < 8; nt++) {
            int j = k0 + nt * 8 + 2 * t;
            if (j >= len)     { sc[nt][0] = -1e30f; sc[nt][2] = -1e30f; }
            if (j + 1 >= len) { sc[nt][1] = -1e30f; sc[nt][3] = -1e30f; }
            mx0 = fmaxf(mx0, fmaxf(sc[nt][0], sc[nt][1]));
            mx1 = fmaxf(mx1, fmaxf(sc[nt][2], sc[nt][3]));
        }
        mx0 = fmaxf(mx0, __shfl_xor_sync(0xffffffffu, mx0, 1));
        mx0 = fmaxf(mx0, __shfl_xor_sync(0xffffffffu, mx0, 2));
        mx1 = fmaxf(mx1, __shfl_xor_sync(0xffffffffu, mx1, 1));
        mx1 = fmaxf(mx1, __shfl_xor_sync(0xffffffffu, mx1, 2));
        float mn0 = fmaxf(m0, mx0), mn1 = fmaxf(m1, mx1);
        float scl0 = __expf(m0 - mn0), scl1 = __expf(m1 - mn1);
        float s0 = 0.f, s1 = 0.f;
#pragma unroll
        for (int nt = 0; nt < 8; nt++) {
            sc[nt][0] = __expf(sc[nt][0] - mn0);
            sc[nt][1] = __expf(sc[nt][1] - mn0);
            sc[nt][2] = __expf(sc[nt][2] - mn1);
            sc[nt][3] = __expf(sc[nt][3] - mn1);
            s0 += sc[nt][0] + sc[nt][1];
            s1 += sc[nt][2] + sc[nt][3];
        }
        s0 += __shfl_xor_sync(0xffffffffu, s0, 1);
        s0 += __shfl_xor_sync(0xffffffffu, s0, 2);
        s1 += __shfl_xor_sync(0xffffffffu, s1, 1);
        s1 += __shfl_xor_sync(0xffffffffu, s1, 2);
        l0 = l0 * scl0 + s0;
        l1 = l1 * scl1 + s1;
#pragma unroll
        for (int dt = 0; dt < 8; dt++) {
            oacc[dt][0] *= scl0; oacc[dt][1] *= scl0;
            oacc[dt][2] *= scl1; oacc[dt][3] *= scl1;
        }
        m0 = mn0; m1 = mn1;

        // O += P V  (P: C layout -> A layout via shfl; V split hi/lo)
#pragma unroll
        for (int kc = 0; kc < 8; kc++) {
            int src0 = (g << 2) + (t >> 1);
            int src1 = src0 + 2;
            float v00 = __shfl_sync(0xffffffffu, sc[kc][0], src0);
            float v01 = __shfl_sync(0xffffffffu, sc[kc][1], src0);
            float v10 = __shfl_sync(0xffffffffu, sc[kc][2], src0);
            float v11 = __shfl_sync(0xffffffffu, sc[kc][3], src0);
            float w00 = __shfl_sync(0xffffffffu, sc[kc][0], src1);
            float w01 = __shfl_sync(0xffffffffu, sc[kc][1], src1);
            float w10 = __shfl_sync(0xffffffffu, sc[kc][2], src1);
            float w11 = __shfl_sync(0xffffffffu, sc[kc][3], src1);
            bool odd = t & 1;
            unsigned a[4];
            a[0] = f2tf(odd ? v01 : v00);
            a[1] = f2tf(odd ? v11 : v10);
            a[2] = f2tf(odd ? w01 : w00);
            a[3] = f2tf(odd ? w11 : w10);
#pragma unroll
            for (int dt = 0; dt < 8; dt++) {
                int vb = (kc * 8 + t) * VS_LD + dt * 8 + g;
                unsigned bh0 = __float_as_uint(Vhi[vb]);
                unsigned bh1 = __float_as_uint(Vhi[vb + 4 * VS_LD]);
                unsigned bl0 = __float_as_uint(Vlo[vb]);
                unsigned bl1 = __float_as_uint(Vlo[vb + 4 * VS_LD]);
                mma_tf32(oacc[dt], a, bh0, bh1);
                mma_tf32(oacc[dt], a, bl0, bl1);
            }
        }
    }

    float il0 = 1.0f / l0, il1 = 1.0f / l1;
    size_t r0 = ((size_t)(b * N + q0 + g)) * HD + h * DH;
    size_t r1 = ((size_t)(b * N + q0 + 8 + g)) * HD + h * DH;
#pragma unroll
    for (int dt = 0; dt < 8; dt++) {
        int col = dt * 8 + 2 * t;
        float2 o0 = { oacc[dt][0] * il0, oacc[dt][1] * il0 };
        float2 o1 = { oacc[dt][2] * il1, oacc[dt][3] * il1 };
        *(float2*)(O + r0 + col) = o0;
        *(float2*)(O + r1 + col) = o1;
    }
}

// ------------- mask output ---------------------------------------------------
__global__ void mask_kernel(const int* __restrict__ lengths, float* __restrict__ out)
{
    int i = blockIdx.x * blockDim.x + threadIdx.x;
    int b = i / N, n = i % N;
    out[i] = (n < lengths[b]) ? 1.0f : 0.0f;
}

// -----------------------------------------------------------------------------
static const int ATTN_SMEM = (2 * 64 * KS_LD + 2 * 64 * VS_LD) * 4; // 71680 B

extern "C" void kernel_launch(void* const* d_in, const int* in_sizes, int n_in,
                              void* d_out, int out_size)
{
    const float* patches    = (const float*)d_in[0];
    const float* pe_ln1_g   = (const float*)d_in[1];
    const float* pe_W       = (const float*)d_in[2];
    const float* pe_b       = (const float*)d_in[3];
    const float* pe_ln2_g   = (const float*)d_in[4];
    const float* attn_ln_g  = (const float*)d_in[5];
    const float* qn_g       = (const float*)d_in[6];
    const float* kn_g       = (const float*)d_in[7];
    const float* Wq         = (const float*)d_in[8];
    const float* Wkv        = (const float*)d_in[9];
    const float* Wo         = (const float*)d_in[10];
    const float* ff_ln_g    = (const float*)d_in[11];
    const float* W1         = (const float*)d_in[12];
    const float* b1         = (const float*)d_in[13];
    const float* W2         = (const float*)d_in[14];
    const float* b2         = (const float*)d_in[15];
    const float* final_ln_g = (const float*)d_in[16];
    const int*   h_idx      = (const int*)d_in[17];
    const int*   w_idx      = (const int*)d_in[18];
    const int*   lengths    = (const int*)d_in[19];
    float* out = (float*)d_out;

    static int attr_set = 0;
    if (!attr_set) {
        cudaFuncSetAttribute(attn_mma, cudaFuncAttributeMaxDynamicSharedMemorySize, ATTN_SMEM);
        attr_set = 1;
    }

    float *x, *xn, *qlin, *kv, *Qb, *Kb, *Vb, *att, *hb;
    cudaGetSymbolAddress((void**)&x, g_x);
    cudaGetSymbolAddress((void**)&xn, g_xn);
    cudaGetSymbolAddress((void**)&qlin, g_qlin);
    cudaGetSymbolAddress((void**)&kv, g_kv);
    cudaGetSymbolAddress((void**)&Qb, g_Q);
    cudaGetSymbolAddress((void**)&Kb, g_K);
    cudaGetSymbolAddress((void**)&Vb, g_V);
    cudaGetSymbolAddress((void**)&att, g_att);
    cudaGetSymbolAddress((void**)&hb, g_h);

    dim3 gDIM(DIM / 128, M / 128);
    dim3 gKV(2 * HD / 128, M / 128);
    dim3 gMLP(MLP / 128, M / 128);

    ln_kernel<<<M, 256>>>(patches, pe_ln1_g, xn);
    gemm_mma<<<gDIM, 256>>>(xn, pe_W, pe_b, nullptr, x, DIM, DIM, 1);
    ln_kernel<<<M, 256>>>(x, pe_ln2_g, x);

    for (int i = 0; i < L; i++) {
        const float* Wq_i  = Wq  + (size_t)i * DIM * HD;
        const float* Wkv_i = Wkv + (size_t)i * DIM * 2 * HD;
        const float* Wo_i  = Wo  + (size_t)i * HD * DIM;
        const float* W1_i  = W1  + (size_t)i * DIM * MLP;
        const float* W2_i  = W2  + (size_t)i * MLP * DIM;

        ln_kernel<<<M, 256>>>(x, attn_ln_g + i * DIM, xn);
        gemm_mma<<<gDIM, 256>>>(xn, Wq_i, nullptr, nullptr, qlin, DIM, HD, 0);
        gemm_mma<<<gKV, 256>>>(xn, Wkv_i, nullptr, nullptr, kv, DIM, 2 * HD, 0);
        qkv_prep<<<(B * H * N) / 8, 256>>>(qlin, kv, qn_g + i * H * DH, kn_g + i * H * DH,
                                           h_idx, w_idx, Qb, Kb, Vb);
        attn_mma<<<dim3(N / 64, B * H), 128, ATTN_SMEM>>>(Qb, Kb, Vb, lengths, att);
        gemm_mma<<<gDIM, 256>>>(att, Wo_i, nullptr, x, x, HD, DIM, 4);
        ln_kernel<<<M, 256>>>(x, ff_ln_g + i * DIM, xn);
        gemm_mma<<<gMLP, 256>>>(xn, W1_i, b1 + i * MLP, nullptr, hb, DIM, MLP, 3);
        gemm_mma<<<gDIM, 256>>>(hb, W2_i, b2 + i * DIM, x, x, MLP, DIM, 5);
    }

    ln_kernel<<<M, 256>>>(x, final_ln_g, out);
    if (out_size >= M * DIM + B * N) {
        mask_kernel<<<(B * N) / 256, 256>>>(lengths, out + (size_t)M * DIM);
    }
}

// round 7
// speedup vs baseline: 4.4995x; 1.0128x over previous
#include <cuda_runtime.h>
#include <math.h>

static constexpr int B = 4, N = 2048, DIM = 768, H = 12, DH = 64, MLP = 3072, L = 2;
static constexpr int M = B * N;            // 8192 rows
static constexpr int HD = H * DH;          // 768

// ---------------- scratch (device globals; no allocation allowed) -------------
__device__ float g_x   [M * DIM];
__device__ float g_xn  [M * DIM];
__device__ float g_qlin[M * HD];
__device__ float g_kv  [M * 2 * HD];
__device__ float g_Q   [B * H * N * DH];
__device__ float g_K   [B * H * N * DH];
__device__ float g_V   [B * H * N * DH];
__device__ float g_att [M * HD];
__device__ float g_h   [M * MLP];

// ---------------- tf32 / async helpers ---------------------------------------
__device__ __forceinline__ unsigned f2tf(float f) {
    unsigned u; asm("cvt.rna.tf32.f32 %0, %1;" : "=r"(u) : "f"(f)); return u;
}

__device__ __forceinline__ void mma_tf32(float* c, const unsigned* a, unsigned b0, unsigned b1) {
    asm volatile("mma.sync.aligned.m16n8k8.row.col.f32.tf32.tf32.f32 "
                 "{%0,%1,%2,%3}, {%4,%5,%6,%7}, {%8,%9}, {%0,%1,%2,%3};"
                 : "+f"(c[0]), "+f"(c[1]), "+f"(c[2]), "+f"(c[3])
                 : "r"(a[0]), "r"(a[1]), "r"(a[2]), "r"(a[3]), "r"(b0), "r"(b1));
}

__device__ __forceinline__ void cp16(float* smem_dst, const float* gsrc) {
    unsigned d = (unsigned)__cvta_generic_to_shared(smem_dst);
    asm volatile("cp.async.cg.shared.global [%0], [%1], 16;" :: "r"(d), "l"(gsrc));
}
__device__ __forceinline__ void cp_commit() { asm volatile("cp.async.commit_group;"); }
__device__ __forceinline__ void cp_wait0()  { asm volatile("cp.async.wait_group 0;"); }

// ---------------- LayerNorm: one warp per row, DIM=768 -----------------------
__global__ void ln_kernel(const float* __restrict__ in, const float* __restrict__ g,
                          float* __restrict__ out)
{
    int warp = (blockIdx.x * blockDim.x + threadIdx.x) >> 5;
    int lane = threadIdx.x & 31;
    const float* x = in + (size_t)warp * DIM;
    float4 v[6];
    float s = 0.f;
#pragma unroll
    for (int i = 0; i < 6; i++) {
        v[i] = *(const float4*)(x + i * 128 + lane * 4);
        s += v[i].x + v[i].y + v[i].z + v[i].w;
    }
#pragma unroll
    for (int o = 16; o; o >>= 1) s += __shfl_xor_sync(0xffffffffu, s, o);
    float mean = s * (1.0f / DIM);
    float s2 = 0.f;
#pragma unroll
    for (int i = 0; i < 6; i++) {
        float a = v[i].x - mean, b = v[i].y - mean, c = v[i].z - mean, d = v[i].w - mean;
        s2 += a * a + b * b + c * c + d * d;
    }
#pragma unroll
    for (int o = 16; o; o >>= 1) s2 += __shfl_xor_sync(0xffffffffu, s2, o);
    float inv = rsqrtf(s2 * (1.0f / DIM) + 1e-5f);
    float* y = out + (size_t)warp * DIM;
#pragma unroll
    for (int i = 0; i < 6; i++) {
        float4 gg = *(const float4*)(g + i * 128 + lane * 4);
        float4 o4;
        o4.x = (v[i].x - mean) * inv * gg.x;
        o4.y = (v[i].y - mean) * inv * gg.y;
        o4.z = (v[i].z - mean) * inv * gg.z;
        o4.w = (v[i].w - mean) * inv * gg.w;
        *(float4*)(y + i * 128 + lane * 4) = o4;
    }
}

// ---------------- tf32 tensor-core GEMM, cp.async double-buffered -------------
#define GBM 128
#define GBN 128
#define GBK 32
#define A_LD 36    // floats; 144B = 9*16 -> cp.async dst 16B aligned
#define B_LD 136   // floats; 544B = 34*16
#define ASZ (GBM * A_LD)   // 4608 floats
#define BSZ (GBK * B_LD)   // 4352 floats
static const int GEMM_SMEM = 2 * (ASZ + BSZ) * 4;  // 71680 B

__global__ __launch_bounds__(256, 2)
void gemm_mma(const float* __restrict__ A, const float* __restrict__ W,
              const float* __restrict__ bias, const float* __restrict__ res,
              float* __restrict__ C, int K_, int Nc, int mode)
{
    extern __shared__ float smg[];
    float* Asm[2] = { smg, smg + ASZ };
    float* Bsm[2] = { smg + 2 * ASZ, smg + 2 * ASZ + BSZ };

    int t = threadIdx.x;
    int warp = t >> 5, lane = t & 31;
    int group = lane >> 2, tid = lane & 3;
    int wm = warp >> 1, wn = warp & 1;
    int wr = wm * 32, wc = wn * 64;
    int m0 = blockIdx.y * GBM, n0 = blockIdx.x * GBN;

    // per-thread staging coords
    int a_row = t >> 3, a_k4 = (t & 7) * 4;        // + i*32 rows
    int b_kr = t >> 5, b_n4 = (t & 31) * 4;        // + i*8 rows

    float acc[2][8][4];
#pragma unroll
    for (int a = 0; a < 2; a++)
#pragma unroll
        for (int b = 0; b < 8; b++)
#pragma unroll
            for (int c = 0; c < 4; c++) acc[a][b][c] = 0.f;

    int KT = K_ / GBK;

    // prologue: stage tile 0
    {
        const float* Ab = A + (size_t)m0 * K_;
        const float* Bb = W + n0;
#pragma unroll
        for (int i = 0; i < 4; i++)
            cp16(&Asm[0][(a_row + i * 32) * A_LD + a_k4], Ab + (size_t)(a_row + i * 32) * K_ + a_k4);
#pragma unroll
        for (int i = 0; i < 4; i++)
            cp16(&Bsm[0][(b_kr + i * 8) * B_LD + b_n4], Bb + (size_t)(b_kr + i * 8) * Nc + b_n4);
        cp_commit();
    }

    for (int kt = 0; kt < KT; kt++) {
        cp_wait0();
        __syncthreads();
        if (kt + 1 < KT) {
            int s = (kt + 1) & 1;
            int k0 = (kt + 1) * GBK;
            const float* Ab = A + (size_t)m0 * K_ + k0;
            const float* Bb = W + (size_t)k0 * Nc + n0;
#pragma unroll
            for (int i = 0; i < 4; i++)
                cp16(&Asm[s][(a_row + i * 32) * A_LD + a_k4], Ab + (size_t)(a_row + i * 32) * K_ + a_k4);
#pragma unroll
            for (int i = 0; i < 4; i++)
                cp16(&Bsm[s][(b_kr + i * 8) * B_LD + b_n4], Bb + (size_t)(b_kr + i * 8) * Nc + b_n4);
            cp_commit();
        }
        const float* As = Asm[kt & 1];
        const float* Bs = Bsm[kt & 1];
#pragma unroll
        for (int kk = 0; kk < 4; kk++) {
            int k8 = kk * 8;
            unsigned a[2][4];
#pragma unroll
            for (int mt = 0; mt < 2; mt++) {
                int r0 = wr + mt * 16;
                a[mt][0] = f2tf(As[(r0 + group) * A_LD + k8 + tid]);
                a[mt][1] = f2tf(As[(r0 + 8 + group) * A_LD + k8 + tid]);
                a[mt][2] = f2tf(As[(r0 + group) * A_LD + k8 + tid + 4]);
                a[mt][3] = f2tf(As[(r0 + 8 + group) * A_LD + k8 + tid + 4]);
            }
#pragma unroll
            for (int nt = 0; nt < 8; nt++) {
                unsigned b0 = f2tf(Bs[(k8 + tid) * B_LD + wc + nt * 8 + group]);
                unsigned b1 = f2tf(Bs[(k8 + tid + 4) * B_LD + wc + nt * 8 + group]);
                mma_tf32(acc[0][nt], a[0], b0, b1);
                mma_tf32(acc[1][nt], a[1], b0, b1);
            }
        }
    }

    // epilogue
#pragma unroll
    for (int mt = 0; mt < 2; mt++) {
#pragma unroll
        for (int half = 0; half < 2; half++) {
            int r = m0 + wr + mt * 16 + half * 8 + group;
#pragma unroll
            for (int nt = 0; nt < 8; nt++) {
                int c = n0 + wc + nt * 8 + tid * 2;
                float v0 = acc[mt][nt][half * 2 + 0];
                float v1 = acc[mt][nt][half * 2 + 1];
                if (mode & 1) { v0 += bias[c]; v1 += bias[c + 1]; }
                if (mode & 2) {
                    v0 = 0.5f * v0 * (1.0f + erff(v0 * 0.70710678118654752f));
                    v1 = 0.5f * v1 * (1.0f + erff(v1 * 0.70710678118654752f));
                }
                if (mode & 4) {
                    float2 rr = *(const float2*)(res + (size_t)r * Nc + c);
                    v0 += rr.x; v1 += rr.y;
                }
                float2 o = { v0, v1 };
                *(float2*)(C + (size_t)r * Nc + c) = o;
            }
        }
    }
}

// ------------- QK rmsnorm + 2D RoPE + V transpose; 1 warp per (b,h,n) --------
__global__ void qkv_prep(const float* __restrict__ qlin, const float* __restrict__ kv,
                         const float* __restrict__ qg, const float* __restrict__ kg,
                         const int* __restrict__ hidx, const int* __restrict__ widx,
                         float* __restrict__ Q, float* __restrict__ K, float* __restrict__ V)
{
    int warp = (blockIdx.x * blockDim.x + threadIdx.x) >> 5;
    int lane = threadIdx.x & 31;
    int n = warp % N;
    int bh = warp / N;
    int h = bh % H, b = bh / H;

    size_t qsrc = ((size_t)(b * N + n)) * HD + h * DH;
    size_t kvsrc = ((size_t)(b * N + n)) * (2 * HD) + h * DH;
    float q0 = qlin[qsrc + lane], q1 = qlin[qsrc + lane + 32];
    float k0 = kv[kvsrc + lane], k1 = kv[kvsrc + lane + 32];
    float v0 = kv[kvsrc + HD + lane], v1 = kv[kvsrc + HD + lane + 32];

    float qs = q0 * q0 + q1 * q1;
    float ks = k0 * k0 + k1 * k1;
    for (int o = 16; o; o >>= 1) {
        qs += __shfl_xor_sync(0xffffffffu, qs, o);
        ks += __shfl_xor_sync(0xffffffffu, ks, o);
    }
    float rq = 8.0f / fmaxf(sqrtf(qs), 1e-12f);
    float rk = 8.0f / fmaxf(sqrtf(ks), 1e-12f);
    q0 = q0 * rq * qg[h * DH + lane];  q1 = q1 * rq * qg[h * DH + lane + 32];
    k0 = k0 * rk * kg[h * DH + lane];  k1 = k1 * rk * kg[h * DH + lane + 32];

    int hv = hidx[b * N + n], wv = widx[b * N + n];
    int fi = lane & 15;
    float invf = __expf(-(float)fi * (9.210340371976184f / 16.0f));
    float th_h = (float)hv * invf, th_w = (float)wv * invf;
    float sh, ch, sw, cw;
    __sincosf(th_h, &sh, &ch);
    __sincosf(th_w, &sw, &cw);
    float sgn = (lane < 16) ? -1.0f : 1.0f;
    float qp0 = __shfl_xor_sync(0xffffffffu, q0, 16);
    float qp1 = __shfl_xor_sync(0xffffffffu, q1, 16);
    float kp0 = __shfl_xor_sync(0xffffffffu, k0, 16);
    float kp1 = __shfl_xor_sync(0xffffffffu, k1, 16);
    q0 = q0 * ch + sgn * qp0 * sh;
    q1 = q1 * cw + sgn * qp1 * sw;
    k0 = k0 * ch + sgn * kp0 * sh;
    k1 = k1 * cw + sgn * kp1 * sw;

    size_t dst = ((size_t)bh * N + n) * DH;
    Q[dst + lane] = q0; Q[dst + lane + 32] = q1;
    K[dst + lane] = k0; K[dst + lane + 32] = k1;
    V[dst + lane] = v0; V[dst + lane + 32] = v1;
}

// ------------- attention: mma flash, 64 queries/block, 64-key tiles ----------
#define KS_LD 68
#define VS_LD 72

__global__ __launch_bounds__(128, 2)
void attn_mma(const float* __restrict__ Q, const float* __restrict__ K,
              const float* __restrict__ V, const int* __restrict__ lengths,
              float* __restrict__ O)
{
    extern __shared__ float sm[];
    float* Khi = sm;
    float* Klo = Khi + 64 * KS_LD;
    float* Vhi = Klo + 64 * KS_LD;
    float* Vlo = Vhi + 64 * VS_LD;

    int bh = blockIdx.y;
    int b = bh / H, h = bh % H;
    int warp = threadIdx.x >> 5, lane = threadIdx.x & 31;
    int g = lane >> 2, t = lane & 3;
    int q0 = blockIdx.x * 64 + warp * 16;
    int len = lengths[b];

    const float* Qb = Q + (size_t)bh * N * DH;
    const float* Kb = K + (size_t)bh * N * DH;
    const float* Vb = V + (size_t)bh * N * DH;

    unsigned qhi[8][4], qlo[8][4];
#pragma unroll
    for (int kk = 0; kk < 8; kk++) {
        float f0 = Qb[(size_t)(q0 + g)     * DH + kk * 8 + t];
        float f1 = Qb[(size_t)(q0 + 8 + g) * DH + kk * 8 + t];
        float f2 = Qb[(size_t)(q0 + g)     * DH + kk * 8 + t + 4];
        float f3 = Qb[(size_t)(q0 + 8 + g) * DH + kk * 8 + t + 4];
        qhi[kk][0] = f2tf(f0); qlo[kk][0] = f2tf(f0 - __uint_as_float(qhi[kk][0]));
        qhi[kk][1] = f2tf(f1); qlo[kk][1] = f2tf(f1 - __uint_as_float(qhi[kk][1]));
        qhi[kk][2] = f2tf(f2); qlo[kk][2] = f2tf(f2 - __uint_as_float(qhi[kk][2]));
        qhi[kk][3] = f2tf(f3); qlo[kk][3] = f2tf(f3 - __uint_as_float(qhi[kk][3]));
    }

    float oacc[8][4];
#pragma unroll
    for (int dt = 0; dt < 8; dt++)
#pragma unroll
        for (int i = 0; i < 4; i++) oacc[dt][i] = 0.f;
    float m0 = -1e30f, m1 = -1e30f, l0 = 0.f, l1 = 0.f;

    for (int k0 = 0; k0 < len; k0 += 64) {
        __syncthreads();
#pragma unroll
        for (int i = 0; i < 8; i++) {
            int idx = threadIdx.x + i * 128;
            int row = idx >> 4, c4 = (idx & 15) * 4;
            int jj = k0 + row; if (jj > N - 1) jj = N - 1;
            float4 kv4 = *(const float4*)(Kb + (size_t)jj * DH + c4);
            float4 vv4 = *(const float4*)(Vb + (size_t)jj * DH + c4);
            float* kh = Khi + row * KS_LD + c4;
            float* kl = Klo + row * KS_LD + c4;
            float* vh = Vhi + row * VS_LD + c4;
            float* vl = Vlo + row * VS_LD + c4;
            float kvv[4] = { kv4.x, kv4.y, kv4.z, kv4.w };
            float vvv[4] = { vv4.x, vv4.y, vv4.z, vv4.w };
#pragma unroll
            for (int j = 0; j < 4; j++) {
                unsigned hbits = f2tf(kvv[j]);
                kh[j] = __uint_as_float(hbits);
                kl[j] = __uint_as_float(f2tf(kvv[j] - __uint_as_float(hbits)));
                unsigned vb = f2tf(vvv[j]);
                vh[j] = __uint_as_float(vb);
                vl[j] = __uint_as_float(f2tf(vvv[j] - __uint_as_float(vb)));
            }
        }
        __syncthreads();

        float sc[8][4];
#pragma unroll
        for (int nt = 0; nt < 8; nt++)
#pragma unroll
            for (int i = 0; i < 4; i++) sc[nt][i] = 0.f;
#pragma unroll
        for (int kk = 0; kk < 8; kk++) {
#pragma unroll
            for (int nt = 0; nt < 8; nt++) {
                int kb = (nt * 8 + g) * KS_LD + kk * 8 + t;
                unsigned bh0 = __float_as_uint(Khi[kb]);
                unsigned bh1 = __float_as_uint(Khi[kb + 4]);
                unsigned bl0 = __float_as_uint(Klo[kb]);
                unsigned bl1 = __float_as_uint(Klo[kb + 4]);
                mma_tf32(sc[nt], qhi[kk], bh0, bh1);
                mma_tf32(sc[nt], qhi[kk], bl0, bl1);
                mma_tf32(sc[nt], qlo[kk], bh0, bh1);
            }
        }

        float mx0 = -1e30f, mx1 = -1e30f;
#pragma unroll
        for (int nt = 0; nt < 8; nt++) {
            int j = k0 + nt * 8 + 2 * t;
            if (j >= len)     { sc[nt][0] = -1e30f; sc[nt][2] = -1e30f; }
            if (j + 1 >= len) { sc[nt][1] = -1e30f; sc[nt][3] = -1e30f; }
            mx0 = fmaxf(mx0, fmaxf(sc[nt][0], sc[nt][1]));
            mx1 = fmaxf(mx1, fmaxf(sc[nt][2], sc[nt][3]));
        }
        mx0 = fmaxf(mx0, __shfl_xor_sync(0xffffffffu, mx0, 1));
        mx0 = fmaxf(mx0, __shfl_xor_sync(0xffffffffu, mx0, 2));
        mx1 = fmaxf(mx1, __shfl_xor_sync(0xffffffffu, mx1, 1));
        mx1 = fmaxf(mx1, __shfl_xor_sync(0xffffffffu, mx1, 2));
        float mn0 = fmaxf(m0, mx0), mn1 = fmaxf(m1, mx1);
        float scl0 = __expf(m0 - mn0), scl1 = __expf(m1 - mn1);
        float s0 = 0.f, s1 = 0.f;
#pragma unroll
        for (int nt = 0; nt < 8; nt++) {
            sc[nt][0] = __expf(sc[nt][0] - mn0);
            sc[nt][1] = __expf(sc[nt][1] - mn0);
            sc[nt][2] = __expf(sc[nt][2] - mn1);
            sc[nt][3] = __expf(sc[nt][3] - mn1);
            s0 += sc[nt][0] + sc[nt][1];
            s1 += sc[nt][2] + sc[nt][3];
        }
        s0 += __shfl_xor_sync(0xffffffffu, s0, 1);
        s0 += __shfl_xor_sync(0xffffffffu, s0, 2);
        s1 += __shfl_xor_sync(0xffffffffu, s1, 1);
        s1 += __shfl_xor_sync(0xffffffffu, s1, 2);
        l0 = l0 * scl0 + s0;
        l1 = l1 * scl1 + s1;
#pragma unroll
        for (int dt = 0; dt < 8; dt++) {
            oacc[dt][0] *= scl0; oacc[dt][1] *= scl0;
            oacc[dt][2] *= scl1; oacc[dt][3] *= scl1;
        }
        m0 = mn0; m1 = mn1;

#pragma unroll
        for (int kc = 0; kc < 8; kc++) {
            int src0 = (g << 2) + (t >> 1);
            int src1 = src0 + 2;
            float v00 = __shfl_sync(0xffffffffu, sc[kc][0], src0);
            float v01 = __shfl_sync(0xffffffffu, sc[kc][1], src0);
            float v10 = __shfl_sync(0xffffffffu, sc[kc][2], src0);
            float v11 = __shfl_sync(0xffffffffu, sc[kc][3], src0);
            float w00 = __shfl_sync(0xffffffffu, sc[kc][0], src1);
            float w01 = __shfl_sync(0xffffffffu, sc[kc][1], src1);
            float w10 = __shfl_sync(0xffffffffu, sc[kc][2], src1);
            float w11 = __shfl_sync(0xffffffffu, sc[kc][3], src1);
            bool odd = t & 1;
            unsigned a[4];
            a[0] = f2tf(odd ? v01 : v00);
            a[1] = f2tf(odd ? v11 : v10);
            a[2] = f2tf(odd ? w01 : w00);
            a[3] = f2tf(odd ? w11 : w10);
#pragma unroll
            for (int dt = 0; dt < 8; dt++) {
                int vb = (kc * 8 + t) * VS_LD + dt * 8 + g;
                unsigned bh0 = __float_as_uint(Vhi[vb]);
                unsigned bh1 = __float_as_uint(Vhi[vb + 4 * VS_LD]);
                unsigned bl0 = __float_as_uint(Vlo[vb]);
                unsigned bl1 = __float_as_uint(Vlo[vb + 4 * VS_LD]);
                mma_tf32(oacc[dt], a, bh0, bh1);
                mma_tf32(oacc[dt], a, bl0, bl1);
            }
        }
    }

    float il0 = 1.0f / l0, il1 = 1.0f / l1;
    size_t r0 = ((size_t)(b * N + q0 + g)) * HD + h * DH;
    size_t r1 = ((size_t)(b * N + q0 + 8 + g)) * HD + h * DH;
#pragma unroll
    for (int dt = 0; dt < 8; dt++) {
        int col = dt * 8 + 2 * t;
        float2 o0 = { oacc[dt][0] * il0, oacc[dt][1] * il0 };
        float2 o1 = { oacc[dt][2] * il1, oacc[dt][3] * il1 };
        *(float2*)(O + r0 + col) = o0;
        *(float2*)(O + r1 + col) = o1;
    }
}

// ------------- mask output ---------------------------------------------------
__global__ void mask_kernel(const int* __restrict__ lengths, float* __restrict__ out)
{
    int i = blockIdx.x * blockDim.x + threadIdx.x;
    int b = i / N, n = i % N;
    out[i] = (n < lengths[b]) ? 1.0f : 0.0f;
}

// -----------------------------------------------------------------------------
static const int ATTN_SMEM = (2 * 64 * KS_LD + 2 * 64 * VS_LD) * 4; // 71680 B

extern "C" void kernel_launch(void* const* d_in, const int* in_sizes, int n_in,
                              void* d_out, int out_size)
{
    const float* patches    = (const float*)d_in[0];
    const float* pe_ln1_g   = (const float*)d_in[1];
    const float* pe_W       = (const float*)d_in[2];
    const float* pe_b       = (const float*)d_in[3];
    const float* pe_ln2_g   = (const float*)d_in[4];
    const float* attn_ln_g  = (const float*)d_in[5];
    const float* qn_g       = (const float*)d_in[6];
    const float* kn_g       = (const float*)d_in[7];
    const float* Wq         = (const float*)d_in[8];
    const float* Wkv        = (const float*)d_in[9];
    const float* Wo         = (const float*)d_in[10];
    const float* ff_ln_g    = (const float*)d_in[11];
    const float* W1         = (const float*)d_in[12];
    const float* b1         = (const float*)d_in[13];
    const float* W2         = (const float*)d_in[14];
    const float* b2         = (const float*)d_in[15];
    const float* final_ln_g = (const float*)d_in[16];
    const int*   h_idx      = (const int*)d_in[17];
    const int*   w_idx      = (const int*)d_in[18];
    const int*   lengths    = (const int*)d_in[19];
    float* out = (float*)d_out;

    cudaFuncSetAttribute(attn_mma, cudaFuncAttributeMaxDynamicSharedMemorySize, ATTN_SMEM);
    cudaFuncSetAttribute(gemm_mma, cudaFuncAttributeMaxDynamicSharedMemorySize, GEMM_SMEM);

    float *x, *xn, *qlin, *kv, *Qb, *Kb, *Vb, *att, *hb;
    cudaGetSymbolAddress((void**)&x, g_x);
    cudaGetSymbolAddress((void**)&xn, g_xn);
    cudaGetSymbolAddress((void**)&qlin, g_qlin);
    cudaGetSymbolAddress((void**)&kv, g_kv);
    cudaGetSymbolAddress((void**)&Qb, g_Q);
    cudaGetSymbolAddress((void**)&Kb, g_K);
    cudaGetSymbolAddress((void**)&Vb, g_V);
    cudaGetSymbolAddress((void**)&att, g_att);
    cudaGetSymbolAddress((void**)&hb, g_h);

    dim3 gDIM(DIM / 128, M / 128);
    dim3 gKV(2 * HD / 128, M / 128);
    dim3 gMLP(MLP / 128, M / 128);

    ln_kernel<<<M / 8, 256>>>(patches, pe_ln1_g, xn);
    gemm_mma<<<gDIM, 256, GEMM_SMEM>>>(xn, pe_W, pe_b, nullptr, x, DIM, DIM, 1);
    ln_kernel<<<M / 8, 256>>>(x, pe_ln2_g, x);

    for (int i = 0; i < L; i++) {
        const float* Wq_i  = Wq  + (size_t)i * DIM * HD;
        const float* Wkv_i = Wkv + (size_t)i * DIM * 2 * HD;
        const float* Wo_i  = Wo  + (size_t)i * HD * DIM;
        const float* W1_i  = W1  + (size_t)i * DIM * MLP;
        const float* W2_i  = W2  + (size_t)i * MLP * DIM;

        ln_kernel<<<M / 8, 256>>>(x, attn_ln_g + i * DIM, xn);
        gemm_mma<<<gDIM, 256, GEMM_SMEM>>>(xn, Wq_i, nullptr, nullptr, qlin, DIM, HD, 0);
        gemm_mma<<<gKV, 256, GEMM_SMEM>>>(xn, Wkv_i, nullptr, nullptr, kv, DIM, 2 * HD, 0);
        qkv_prep<<<(B * H * N) / 8, 256>>>(qlin, kv, qn_g + i * H * DH, kn_g + i * H * DH,
                                           h_idx, w_idx, Qb, Kb, Vb);
        attn_mma<<<dim3(N / 64, B * H), 128, ATTN_SMEM>>>(Qb, Kb, Vb, lengths, att);
        gemm_mma<<<gDIM, 256, GEMM_SMEM>>>(att, Wo_i, nullptr, x, x, HD, DIM, 4);
        ln_kernel<<<M / 8, 256>>>(x, ff_ln_g + i * DIM, xn);
        gemm_mma<<<gMLP, 256, GEMM_SMEM>>>(xn, W1_i, b1 + i * MLP, nullptr, hb, DIM, MLP, 3);
        gemm_mma<<<gDIM, 256, GEMM_SMEM>>>(hb, W2_i, b2 + i * DIM, x, x, MLP, DIM, 5);
    }

    ln_kernel<<<M / 8, 256>>>(x, final_ln_g, out);
    if (out_size >= M * DIM + B * N) {
        mask_kernel<<<(B * N) / 256, 256>>>(lengths, out + (size_t)M * DIM);
    }
}